// round 14
// baseline (speedup 1.0000x reference)
#include <cuda_runtime.h>
#include <cuda_fp16.h>
#include <cstdint>

#define BATCH 64
#define NSEQ  2048
#define CDIM  128
#define HP    64
#define WP    32
#define HG    32   // HP / POOL
#define D_SCALE 0.08838834764831845f  // 1/sqrt(128)

// Scratch: Q,K,V in [B, C, N] (spatial-major) layout. V plane is overwritten
// with the attention output by attn_kernel (each CTA exclusively owns its plane,
// and proj writes it fully on every graph replay -> deterministic).
__device__ float g_QT[(size_t)BATCH * CDIM * NSEQ];
__device__ float g_KT[(size_t)BATCH * CDIM * NSEQ];
__device__ float g_VT[(size_t)BATCH * CDIM * NSEQ];

// Precomputed W fragments (fp16, 2-ks packed):
// [p][(nt*4+kp)*32+lane] -> uint4 (b0@ks=2kp, b1@ks=2kp, b0@ks=2kp+1, b1@ks=2kp+1)
__device__ uint4 g_Wpk[3 * 2048];

#define SSTR 132   // proj epilogue transpose-buffer row stride (floats)

__device__ __forceinline__ uint32_t h2u(__half2 h) {
    return *reinterpret_cast<uint32_t*>(&h);
}

__device__ __forceinline__ void mma_f16(float& d0, float& d1, float& d2, float& d3,
                                        uint32_t a0, uint32_t a1, uint32_t a2, uint32_t a3,
                                        uint32_t b0, uint32_t b1) {
    asm volatile(
        "mma.sync.aligned.m16n8k16.row.col.f32.f16.f16.f32 "
        "{%0,%1,%2,%3}, {%4,%5,%6,%7}, {%8,%9}, {%0,%1,%2,%3};"
        : "+f"(d0), "+f"(d1), "+f"(d2), "+f"(d3)
        : "r"(a0), "r"(a1), "r"(a2), "r"(a3), "r"(b0), "r"(b1));
}

// ---------------------------------------------------------------------------
// Kernel 0: convert W matrices into 2-ks-packed fp16 MMA fragments, once.
// ---------------------------------------------------------------------------
__global__ __launch_bounds__(256) void prep_w_kernel(
    const float* __restrict__ Wq, const float* __restrict__ Wk,
    const float* __restrict__ Wv)
{
    const int p = blockIdx.x;
    const float* W = (p == 0) ? Wq : (p == 1) ? Wk : Wv;
    const int t = threadIdx.x;
    #pragma unroll
    for (int i = 0; i < 8; ++i) {
        const int pos  = t + i * 256;        // 0..2047
        const int lane = pos & 31;
        const int kp   = (pos >> 5) & 3;
        const int nt   = pos >> 7;
        const int gj   = lane >> 2;
        const int s    = lane & 3;
        const int j    = nt * 8 + gj;
        const int ca   = (2 * kp) * 16 + 2 * s;
        const int cb   = ca + 16;
        __half2 x = __floats2half2_rn(W[j * CDIM + ca],     W[j * CDIM + ca + 1]);
        __half2 y = __floats2half2_rn(W[j * CDIM + ca + 8], W[j * CDIM + ca + 9]);
        __half2 z = __floats2half2_rn(W[j * CDIM + cb],     W[j * CDIM + cb + 1]);
        __half2 w = __floats2half2_rn(W[j * CDIM + cb + 8], W[j * CDIM + cb + 9]);
        g_Wpk[p * 2048 + pos] = make_uint4(h2u(x), h2u(y), h2u(z), h2u(w));
    }
}

// ---------------------------------------------------------------------------
// Kernel 1: projection GEMMs (proven R13 version).
// ---------------------------------------------------------------------------
__global__ __launch_bounds__(512) void proj_mma_kernel(
    const float* __restrict__ X,
    const float* __restrict__ bq, const float* __restrict__ bk,
    const float* __restrict__ bv)
{
    extern __shared__ uint4 smq[];
    uint4* Apk = smq;               // [8 mt][8 ks][32 lane]  2048 uint4 (32 KB)
    uint4* Wpk = smq + 2048;        // [16 nt][4 kp][32 lane] 2048 uint4 (32 KB)
    float* T   = (float*)(smq + 4096);  // [128 j][SSTR] transpose buf (67.6 KB)

    const int t    = threadIdx.x;
    const int warp = t >> 5;
    const int lane = t & 31;
    const int M0   = blockIdx.x * 128;
    const int bidx = M0 >> 11;
    const int n0   = M0 & 2047;

    const int g      = lane >> 2;
    const int tid    = lane & 3;
    const int mgroup = warp & 7;
    const int nhalf  = warp >> 3;
    const int mbase  = mgroup * 16;

    // ---- Stage A: pack X into fp16 MMA fragments (once, reused for 3 p's) ----
    #pragma unroll
    for (int i = 0; i < 4; ++i) {
        const int pos = t + i * 512;          // 0..2047
        const int ln  = pos & 31;
        const int ks  = (pos >> 5) & 7;
        const int mt  = pos >> 8;
        const int gg  = ln >> 2;
        const int ss  = ln & 3;
        const int r0  = M0 + mt * 16 + gg;
        const int c0  = ks * 16 + 2 * ss;
        float2 x00 = *(const float2*)(X + (size_t)r0 * CDIM + c0);
        float2 x10 = *(const float2*)(X + (size_t)(r0 + 8) * CDIM + c0);
        float2 x02 = *(const float2*)(X + (size_t)r0 * CDIM + c0 + 8);
        float2 x12 = *(const float2*)(X + (size_t)(r0 + 8) * CDIM + c0 + 8);
        Apk[pos] = make_uint4(h2u(__floats2half2_rn(x00.x, x00.y)),
                              h2u(__floats2half2_rn(x10.x, x10.y)),
                              h2u(__floats2half2_rn(x02.x, x02.y)),
                              h2u(__floats2half2_rn(x12.x, x12.y)));
    }

    #pragma unroll 1
    for (int p = 0; p < 3; ++p) {
        const float* bias = (p == 0) ? bq : (p == 1) ? bk : bv;
        float* OutT       = (p == 0) ? g_QT : (p == 1) ? g_KT : g_VT;

        // ---- Stage W fragments: straight copy (2048 uint4) ----
        #pragma unroll
        for (int i = 0; i < 4; ++i)
            Wpk[t + i * 512] = g_Wpk[p * 2048 + t + i * 512];
        __syncthreads();

        // ---- MMA mainloop: warp owns 16 m-rows x 64 j-cols (8 nt) ----
        float acc[8][4];
        #pragma unroll
        for (int nt = 0; nt < 8; ++nt)
            #pragma unroll
            for (int q = 0; q < 4; ++q) acc[nt][q] = 0.0f;

        #pragma unroll
        for (int kp = 0; kp < 4; ++kp) {
            uint4 Aa = Apk[(mgroup * 8 + 2 * kp) * 32 + lane];
            uint4 Ab = Apk[(mgroup * 8 + 2 * kp + 1) * 32 + lane];
            #pragma unroll
            for (int nt = 0; nt < 8; ++nt) {
                const int ntg = nhalf * 8 + nt;
                uint4 w = Wpk[(ntg * 4 + kp) * 32 + lane];
                mma_f16(acc[nt][0], acc[nt][1], acc[nt][2], acc[nt][3],
                        Aa.x, Aa.y, Aa.z, Aa.w, w.x, w.y);
                mma_f16(acc[nt][0], acc[nt][1], acc[nt][2], acc[nt][3],
                        Ab.x, Ab.y, Ab.z, Ab.w, w.z, w.w);
            }
        }

        // ---- Epilogue: bias + sigmoid, transpose to [j][m] via T ----
        #pragma unroll
        for (int nt = 0; nt < 8; ++nt) {
            const int j0 = nhalf * 64 + nt * 8 + 2 * tid;
            const float b0v = __ldg(bias + j0);
            const float b1v = __ldg(bias + j0 + 1);
            float v0 = acc[nt][0] + b0v;
            float v1 = acc[nt][1] + b1v;
            float v2 = acc[nt][2] + b0v;
            float v3 = acc[nt][3] + b1v;
            v0 = 1.0f / (1.0f + __expf(-v0));
            v1 = 1.0f / (1.0f + __expf(-v1));
            v2 = 1.0f / (1.0f + __expf(-v2));
            v3 = 1.0f / (1.0f + __expf(-v3));
            T[j0 * SSTR + mbase + g]           = v0;
            T[(j0 + 1) * SSTR + mbase + g]     = v1;
            T[j0 * SSTR + mbase + g + 8]       = v2;
            T[(j0 + 1) * SSTR + mbase + g + 8] = v3;
        }
        __syncthreads();

        // ---- Coalesced float4 store: OutT[bidx][j][n0 + m] ----
        #pragma unroll
        for (int it = 0; it < 8; ++it) {
            const int idx = t + it * 512;
            const int j   = idx >> 5;
            const int m4  = (idx & 31) << 2;
            float4 v = *(const float4*)(T + j * SSTR + m4);
            *(float4*)(OutT + ((size_t)bidx * CDIM + j) * NSEQ + n0 + m4) = v;
        }
        __syncthreads();   // stores read T; next p overwrites Wpk (disjoint) + T
    }
}

// ---------------------------------------------------------------------------
// Kernel 2: per-(b,c) dual-softmax attention (R12 packed version), with the
// Qs buffer ELIMINATED: pooled q is computed in the load loop via shfl_xor
// (threads t and t^8 hold the h / h+1 row pair for the same w chunk).
// Static smem 53.5KB -> 45.3KB => 5 CTAs/SM instead of 4.
// Arithmetic (operands + order) identical to R13 -> bit-identical results.
// ---------------------------------------------------------------------------
__global__ __launch_bounds__(256) void attn_kernel()
{
    const int bc = blockIdx.x;                      // b*128 + c
    const float* Qp = g_QT + (size_t)bc * NSEQ;
    const float* Kp = g_KT + (size_t)bc * NSEQ;
    const float* Vp = g_VT + (size_t)bc * NSEQ;
    float* Op = g_VT + (size_t)bc * NSEQ;           // overwrite V plane

    __shared__ float Vs[HP * WP];     // [h][w]
    __shared__ float KTs[WP * 65];    // [w][h], padded
    __shared__ float kTs[WP * 33];    // [w][g], pooled K, padded
    __shared__ float qpk[8 * 128];    // pooled q packed: [g>>2][w*4+(g&3)]
    __shared__ float Qpk[8 * 256];    // Q packed: [h>>3][w*8+(h&7)]
    __shared__ float Kqvs[HG * WP];   // [g][w]
    __shared__ float Ppk[8 * 256];    // probs packed (phase A->B, then C->D)

    const int t    = threadIdx.x;
    const int warp = t >> 5;
    const int lane = t & 31;
    const unsigned FULL = 0xffffffffu;

    // ---- Load; K transposed; Q packed [w][hi]; pooled q via shfl pairs ----
    #pragma unroll
    for (int i = 0; i < 2; ++i) {
        int idx = (t + i * 256) * 4;
        float4 qv = *(const float4*)(Qp + idx);
        float4 vv = *(const float4*)(Vp + idx);
        float4 kv = *(const float4*)(Kp + idx);
        *(float4*)(Vs + idx) = vv;
        int h = idx >> 5, w = idx & 31;
        KTs[(w + 0) * 65 + h] = kv.x;
        KTs[(w + 1) * 65 + h] = kv.y;
        KTs[(w + 2) * 65 + h] = kv.z;
        KTs[(w + 3) * 65 + h] = kv.w;
        float* qd = Qpk + (h >> 3) * 256 + (h & 7);
        qd[(w + 0) * 8] = qv.x;
        qd[(w + 1) * 8] = qv.y;
        qd[(w + 2) * 8] = qv.z;
        qd[(w + 3) * 8] = qv.w;
        // pooled q: partner thread (lane^8) holds row h^1, same w chunk
        float px = __shfl_xor_sync(FULL, qv.x, 8);
        float py = __shfl_xor_sync(FULL, qv.y, 8);
        float pz = __shfl_xor_sync(FULL, qv.z, 8);
        float pw = __shfl_xor_sync(FULL, qv.w, 8);
        if ((h & 1) == 0) {
            const int gq = h >> 1;
            float* qq = qpk + (gq >> 2) * 128 + (gq & 3);
            qq[(w + 0) * 4] = 0.5f * (qv.x + px);
            qq[(w + 1) * 4] = 0.5f * (qv.y + py);
            qq[(w + 2) * 4] = 0.5f * (qv.z + pz);
            qq[(w + 3) * 4] = 0.5f * (qv.w + pw);
        }
    }
    __syncthreads();

    // ---- Pool K over h pairs ----
    #pragma unroll
    for (int i = 0; i < 4; ++i) {
        int idx = t + i * 256;
        int g = idx >> 5, w = idx & 31;
        kTs[w * 33 + g] = 0.5f * (KTs[w * 65 + 2 * g] + KTs[w * 65 + 2 * g + 1]);
    }
    __syncthreads();

    const int g0 = warp * 4;
    {
        float s0[4] = {0, 0, 0, 0}, s1[4] = {0, 0, 0, 0};
        #pragma unroll
        for (int w = 0; w < 32; ++w) {
            float k0 = KTs[w * 65 + lane];
            float k1 = KTs[w * 65 + 32 + lane];
            float4 qv = *(const float4*)(qpk + warp * 128 + w * 4);
            s0[0] = fmaf(qv.x, k0, s0[0]);  s1[0] = fmaf(qv.x, k1, s1[0]);
            s0[1] = fmaf(qv.y, k0, s0[1]);  s1[1] = fmaf(qv.y, k1, s1[1]);
            s0[2] = fmaf(qv.z, k0, s0[2]);  s1[2] = fmaf(qv.z, k1, s1[2]);
            s0[3] = fmaf(qv.w, k0, s0[3]);  s1[3] = fmaf(qv.w, k1, s1[3]);
        }
        float p0[4], p1[4];
        #pragma unroll
        for (int gi = 0; gi < 4; ++gi) {
            float a = s0[gi] * D_SCALE, b = s1[gi] * D_SCALE;
            float m = fmaxf(a, b);
            #pragma unroll
            for (int o = 16; o; o >>= 1) m = fmaxf(m, __shfl_xor_sync(FULL, m, o));
            float e0 = __expf(a - m), e1 = __expf(b - m);
            float sum = e0 + e1;
            #pragma unroll
            for (int o = 16; o; o >>= 1) sum += __shfl_xor_sync(FULL, sum, o);
            float r = __frcp_rn(sum);
            p0[gi] = e0 * r;
            p1[gi] = e1 * r;
        }
        *(float4*)(Ppk + warp * 256 + lane * 4)        = make_float4(p0[0], p0[1], p0[2], p0[3]);
        *(float4*)(Ppk + warp * 256 + (lane + 32) * 4) = make_float4(p1[0], p1[1], p1[2], p1[3]);
        __syncwarp();

        float acc[4] = {0, 0, 0, 0};
        #pragma unroll 8
        for (int h = 0; h < 64; ++h) {
            float4 p = *(const float4*)(Ppk + warp * 256 + h * 4);
            float v = Vs[h * 32 + lane];
            acc[0] = fmaf(p.x, v, acc[0]);
            acc[1] = fmaf(p.y, v, acc[1]);
            acc[2] = fmaf(p.z, v, acc[2]);
            acc[3] = fmaf(p.w, v, acc[3]);
        }
        Kqvs[(g0 + 0) * 32 + lane] = acc[0];
        Kqvs[(g0 + 1) * 32 + lane] = acc[1];
        Kqvs[(g0 + 2) * 32 + lane] = acc[2];
        Kqvs[(g0 + 3) * 32 + lane] = acc[3];
    }
    __syncthreads();

    const int h0 = warp * 8;
    {
        float s[8] = {0, 0, 0, 0, 0, 0, 0, 0};
        #pragma unroll
        for (int w = 0; w < 32; ++w) {
            float kt = kTs[w * 33 + lane];
            float4 qa = *(const float4*)(Qpk + warp * 256 + w * 8);
            float4 qb = *(const float4*)(Qpk + warp * 256 + w * 8 + 4);
            s[0] = fmaf(qa.x, kt, s[0]);
            s[1] = fmaf(qa.y, kt, s[1]);
            s[2] = fmaf(qa.z, kt, s[2]);
            s[3] = fmaf(qa.w, kt, s[3]);
            s[4] = fmaf(qb.x, kt, s[4]);
            s[5] = fmaf(qb.y, kt, s[5]);
            s[6] = fmaf(qb.z, kt, s[6]);
            s[7] = fmaf(qb.w, kt, s[7]);
        }
        float p2[8];
        #pragma unroll
        for (int hi = 0; hi < 8; ++hi) {
            float a = s[hi] * D_SCALE;
            float m = a;
            #pragma unroll
            for (int o = 16; o; o >>= 1) m = fmaxf(m, __shfl_xor_sync(FULL, m, o));
            float e = __expf(a - m);
            float sum = e;
            #pragma unroll
            for (int o = 16; o; o >>= 1) sum += __shfl_xor_sync(FULL, sum, o);
            p2[hi] = e * __frcp_rn(sum);
        }
        *(float4*)(Ppk + warp * 256 + lane * 8)     = make_float4(p2[0], p2[1], p2[2], p2[3]);
        *(float4*)(Ppk + warp * 256 + lane * 8 + 4) = make_float4(p2[4], p2[5], p2[6], p2[7]);
        __syncwarp();

        float acc[8] = {0, 0, 0, 0, 0, 0, 0, 0};
        #pragma unroll 8
        for (int g = 0; g < 32; ++g) {
            float4 pa = *(const float4*)(Ppk + warp * 256 + g * 8);
            float4 pb = *(const float4*)(Ppk + warp * 256 + g * 8 + 4);
            float kv = Kqvs[g * 32 + lane];
            acc[0] = fmaf(pa.x, kv, acc[0]);
            acc[1] = fmaf(pa.y, kv, acc[1]);
            acc[2] = fmaf(pa.z, kv, acc[2]);
            acc[3] = fmaf(pa.w, kv, acc[3]);
            acc[4] = fmaf(pb.x, kv, acc[4]);
            acc[5] = fmaf(pb.y, kv, acc[5]);
            acc[6] = fmaf(pb.z, kv, acc[6]);
            acc[7] = fmaf(pb.w, kv, acc[7]);
        }
        #pragma unroll
        for (int hi = 0; hi < 8; ++hi)
            Op[(h0 + hi) * 32 + lane] = acc[hi];
    }
}

// ---------------------------------------------------------------------------
// Kernel 3: [B, C, N] -> [B, N, C] transpose (output epilogue).
// ---------------------------------------------------------------------------
__global__ __launch_bounds__(256) void transpose_kernel(float* __restrict__ out)
{
    __shared__ float tile[32][33];
    const int b  = blockIdx.z;
    const int c0 = blockIdx.y * 32;
    const int n0 = blockIdx.x * 32;
    const int tx = threadIdx.x;
    const int ty = threadIdx.y;

    const float* src = g_VT + (size_t)b * CDIM * NSEQ;
    #pragma unroll
    for (int i = 0; i < 32; i += 8)
        tile[ty + i][tx] = src[(size_t)(c0 + ty + i) * NSEQ + n0 + tx];
    __syncthreads();
    #pragma unroll
    for (int i = 0; i < 32; i += 8)
        out[((size_t)b * NSEQ + n0 + ty + i) * CDIM + c0 + tx] = tile[tx][ty + i];
}

// ---------------------------------------------------------------------------
extern "C" void kernel_launch(void* const* d_in, const int* in_sizes, int n_in,
                              void* d_out, int out_size)
{
    (void)in_sizes; (void)n_in; (void)out_size;
    const float* X  = (const float*)d_in[0];
    const float* Wq = (const float*)d_in[1];
    const float* bq = (const float*)d_in[2];
    const float* Wk = (const float*)d_in[3];
    const float* bk = (const float*)d_in[4];
    const float* Wv = (const float*)d_in[5];
    const float* bv = (const float*)d_in[6];
    float* out = (float*)d_out;

    // Apk (32KB) + Wpk (32KB) + T (128*SSTR*4 = 67584B) = 133120 B
    const size_t proj_smem = 4096 * sizeof(uint4) + (size_t)128 * SSTR * sizeof(float);
    cudaFuncSetAttribute(proj_mma_kernel, cudaFuncAttributeMaxDynamicSharedMemorySize,
                         (int)proj_smem);

    prep_w_kernel<<<dim3(3, 1, 1), 256>>>(Wq, Wk, Wv);
    proj_mma_kernel<<<dim3(1024, 1, 1), 512, proj_smem>>>(X, bq, bk, bv);
    attn_kernel<<<dim3(BATCH * CDIM, 1, 1), 256>>>();
    transpose_kernel<<<dim3(NSEQ / 32, CDIM / 32, BATCH), dim3(32, 8, 1)>>>(out);
}

// round 15
// speedup vs baseline: 1.0631x; 1.0631x over previous
#include <cuda_runtime.h>
#include <cuda_fp16.h>
#include <cstdint>

#define BATCH 64
#define NSEQ  2048
#define CDIM  128
#define HP    64
#define WP    32
#define HG    32   // HP / POOL
#define D_SCALE 0.08838834764831845f  // 1/sqrt(128)

// Scratch: Q,K,V in [B, C, N] (spatial-major) layout, fp16 (sigmoid outputs in
// (0,1): quantization ~2^-11 rel, well inside the measured error budget).
// Attention output goes to the dedicated fp32 buffer g_O.
__device__ __half g_Qh[(size_t)BATCH * CDIM * NSEQ];
__device__ __half g_Kh[(size_t)BATCH * CDIM * NSEQ];
__device__ __half g_Vh[(size_t)BATCH * CDIM * NSEQ];
__device__ float  g_O [(size_t)BATCH * CDIM * NSEQ];

// Precomputed W fragments (fp16, 2-ks packed):
// [p][(nt*4+kp)*32+lane] -> uint4 (b0@ks=2kp, b1@ks=2kp, b0@ks=2kp+1, b1@ks=2kp+1)
__device__ uint4 g_Wpk[3 * 2048];

#define TSTR 136   // proj epilogue half-transpose-buffer row stride (halves; 272B, 16B-aligned rows)

__device__ __forceinline__ uint32_t h2u(__half2 h) {
    return *reinterpret_cast<uint32_t*>(&h);
}

__device__ __forceinline__ void mma_f16(float& d0, float& d1, float& d2, float& d3,
                                        uint32_t a0, uint32_t a1, uint32_t a2, uint32_t a3,
                                        uint32_t b0, uint32_t b1) {
    asm volatile(
        "mma.sync.aligned.m16n8k16.row.col.f32.f16.f16.f32 "
        "{%0,%1,%2,%3}, {%4,%5,%6,%7}, {%8,%9}, {%0,%1,%2,%3};"
        : "+f"(d0), "+f"(d1), "+f"(d2), "+f"(d3)
        : "r"(a0), "r"(a1), "r"(a2), "r"(a3), "r"(b0), "r"(b1));
}

// ---------------------------------------------------------------------------
// Kernel 0: convert W matrices into 2-ks-packed fp16 MMA fragments, once.
// ---------------------------------------------------------------------------
__global__ __launch_bounds__(256) void prep_w_kernel(
    const float* __restrict__ Wq, const float* __restrict__ Wk,
    const float* __restrict__ Wv)
{
    const int p = blockIdx.x;
    const float* W = (p == 0) ? Wq : (p == 1) ? Wk : Wv;
    const int t = threadIdx.x;
    #pragma unroll
    for (int i = 0; i < 8; ++i) {
        const int pos  = t + i * 256;        // 0..2047
        const int lane = pos & 31;
        const int kp   = (pos >> 5) & 3;
        const int nt   = pos >> 7;
        const int gj   = lane >> 2;
        const int s    = lane & 3;
        const int j    = nt * 8 + gj;
        const int ca   = (2 * kp) * 16 + 2 * s;
        const int cb   = ca + 16;
        __half2 x = __floats2half2_rn(W[j * CDIM + ca],     W[j * CDIM + ca + 1]);
        __half2 y = __floats2half2_rn(W[j * CDIM + ca + 8], W[j * CDIM + ca + 9]);
        __half2 z = __floats2half2_rn(W[j * CDIM + cb],     W[j * CDIM + cb + 1]);
        __half2 w = __floats2half2_rn(W[j * CDIM + cb + 8], W[j * CDIM + cb + 9]);
        g_Wpk[p * 2048 + pos] = make_uint4(h2u(x), h2u(y), h2u(z), h2u(w));
    }
}

// ---------------------------------------------------------------------------
// Kernel 1: projection GEMMs (R13 structure); output stored as fp16.
// Epilogue transpose buffer is half (34 KB), global stores are 8-half uint4s.
// ---------------------------------------------------------------------------
__global__ __launch_bounds__(512) void proj_mma_kernel(
    const float* __restrict__ X,
    const float* __restrict__ bq, const float* __restrict__ bk,
    const float* __restrict__ bv)
{
    extern __shared__ uint4 smq[];
    uint4*  Apk = smq;               // [8 mt][8 ks][32 lane]  2048 uint4 (32 KB)
    uint4*  Wpk = smq + 2048;        // [16 nt][4 kp][32 lane] 2048 uint4 (32 KB)
    __half* Th  = (__half*)(smq + 4096);  // [128 j][TSTR] half transpose buf (34 KB)

    const int t    = threadIdx.x;
    const int warp = t >> 5;
    const int lane = t & 31;
    const int M0   = blockIdx.x * 128;
    const int bidx = M0 >> 11;
    const int n0   = M0 & 2047;

    const int g      = lane >> 2;
    const int tid    = lane & 3;
    const int mgroup = warp & 7;
    const int nhalf  = warp >> 3;
    const int mbase  = mgroup * 16;

    // ---- Stage A: pack X into fp16 MMA fragments (once, reused for 3 p's) ----
    #pragma unroll
    for (int i = 0; i < 4; ++i) {
        const int pos = t + i * 512;          // 0..2047
        const int ln  = pos & 31;
        const int ks  = (pos >> 5) & 7;
        const int mt  = pos >> 8;
        const int gg  = ln >> 2;
        const int ss  = ln & 3;
        const int r0  = M0 + mt * 16 + gg;
        const int c0  = ks * 16 + 2 * ss;
        float2 x00 = *(const float2*)(X + (size_t)r0 * CDIM + c0);
        float2 x10 = *(const float2*)(X + (size_t)(r0 + 8) * CDIM + c0);
        float2 x02 = *(const float2*)(X + (size_t)r0 * CDIM + c0 + 8);
        float2 x12 = *(const float2*)(X + (size_t)(r0 + 8) * CDIM + c0 + 8);
        Apk[pos] = make_uint4(h2u(__floats2half2_rn(x00.x, x00.y)),
                              h2u(__floats2half2_rn(x10.x, x10.y)),
                              h2u(__floats2half2_rn(x02.x, x02.y)),
                              h2u(__floats2half2_rn(x12.x, x12.y)));
    }

    #pragma unroll 1
    for (int p = 0; p < 3; ++p) {
        const float* bias = (p == 0) ? bq : (p == 1) ? bk : bv;
        __half* OutT      = (p == 0) ? g_Qh : (p == 1) ? g_Kh : g_Vh;

        // ---- Stage W fragments: straight copy (2048 uint4) ----
        #pragma unroll
        for (int i = 0; i < 4; ++i)
            Wpk[t + i * 512] = g_Wpk[p * 2048 + t + i * 512];
        __syncthreads();

        // ---- MMA mainloop: warp owns 16 m-rows x 64 j-cols (8 nt) ----
        float acc[8][4];
        #pragma unroll
        for (int nt = 0; nt < 8; ++nt)
            #pragma unroll
            for (int q = 0; q < 4; ++q) acc[nt][q] = 0.0f;

        #pragma unroll
        for (int kp = 0; kp < 4; ++kp) {
            uint4 Aa = Apk[(mgroup * 8 + 2 * kp) * 32 + lane];
            uint4 Ab = Apk[(mgroup * 8 + 2 * kp + 1) * 32 + lane];
            #pragma unroll
            for (int nt = 0; nt < 8; ++nt) {
                const int ntg = nhalf * 8 + nt;
                uint4 w = Wpk[(ntg * 4 + kp) * 32 + lane];
                mma_f16(acc[nt][0], acc[nt][1], acc[nt][2], acc[nt][3],
                        Aa.x, Aa.y, Aa.z, Aa.w, w.x, w.y);
                mma_f16(acc[nt][0], acc[nt][1], acc[nt][2], acc[nt][3],
                        Ab.x, Ab.y, Ab.z, Ab.w, w.z, w.w);
            }
        }

        // ---- Epilogue: bias + sigmoid -> half, transpose to [j][m] via Th ----
        #pragma unroll
        for (int nt = 0; nt < 8; ++nt) {
            const int j0 = nhalf * 64 + nt * 8 + 2 * tid;
            const float b0v = __ldg(bias + j0);
            const float b1v = __ldg(bias + j0 + 1);
            float v0 = acc[nt][0] + b0v;
            float v1 = acc[nt][1] + b1v;
            float v2 = acc[nt][2] + b0v;
            float v3 = acc[nt][3] + b1v;
            v0 = 1.0f / (1.0f + __expf(-v0));
            v1 = 1.0f / (1.0f + __expf(-v1));
            v2 = 1.0f / (1.0f + __expf(-v2));
            v3 = 1.0f / (1.0f + __expf(-v3));
            Th[j0 * TSTR + mbase + g]           = __float2half_rn(v0);
            Th[(j0 + 1) * TSTR + mbase + g]     = __float2half_rn(v1);
            Th[j0 * TSTR + mbase + g + 8]       = __float2half_rn(v2);
            Th[(j0 + 1) * TSTR + mbase + g + 8] = __float2half_rn(v3);
        }
        __syncthreads();

        // ---- Coalesced uint4 (8-half) store: OutT[bidx][j][n0 + m] ----
        #pragma unroll
        for (int it = 0; it < 4; ++it) {
            const int idx = t + it * 512;     // 0..2047
            const int j   = idx >> 4;
            const int m8  = (idx & 15) << 3;
            uint4 v = *(const uint4*)(Th + j * TSTR + m8);
            *(uint4*)(OutT + ((size_t)bidx * CDIM + j) * NSEQ + n0 + m8) = v;
        }
        __syncthreads();   // stores read Th; next p overwrites Wpk + Th
    }
}

// ---------------------------------------------------------------------------
// Kernel 2: per-(b,c) dual-softmax attention (proven R12/R13 packed version);
// loads fp16 Q/K/V and converts to fp32 at staging. Output fp32 to g_O.
// ---------------------------------------------------------------------------
__global__ __launch_bounds__(256) void attn_kernel()
{
    const int bc = blockIdx.x;                      // b*128 + c
    const __half* Qp = g_Qh + (size_t)bc * NSEQ;
    const __half* Kp = g_Kh + (size_t)bc * NSEQ;
    const __half* Vp = g_Vh + (size_t)bc * NSEQ;
    float* Op = g_O + (size_t)bc * NSEQ;

    __shared__ float Qs[HP * WP];     // [h][w]
    __shared__ float Vs[HP * WP];     // [h][w]
    __shared__ float KTs[WP * 65];    // [w][h], padded
    __shared__ float kTs[WP * 33];    // [w][g], pooled K, padded
    __shared__ float qpk[8 * 128];    // pooled q packed: [g>>2][w*4+(g&3)]
    __shared__ float Qpk[8 * 256];    // Q packed: [h>>3][w*8+(h&7)]
    __shared__ float Kqvs[HG * WP];   // [g][w]
    __shared__ float Ppk[8 * 256];    // probs packed (phase A->B, then C->D)

    const int t    = threadIdx.x;
    const int warp = t >> 5;
    const int lane = t & 31;
    const unsigned FULL = 0xffffffffu;

    // ---- Load 8 halves per array per thread; convert; K transposed; Q packed ----
    {
        const int idx = t * 8;                // 0..2040
        const int h = idx >> 5, w = idx & 31; // w in {0,8,16,24}
        uint4 qr = *(const uint4*)(Qp + idx);
        uint4 vr = *(const uint4*)(Vp + idx);
        uint4 kr = *(const uint4*)(Kp + idx);
        float q[8], v[8], k[8];
        {
            const __half2* qh = (const __half2*)&qr;
            const __half2* vh = (const __half2*)&vr;
            const __half2* kh = (const __half2*)&kr;
            #pragma unroll
            for (int i = 0; i < 4; ++i) {
                float2 f;
                f = __half22float2(qh[i]); q[2 * i] = f.x; q[2 * i + 1] = f.y;
                f = __half22float2(vh[i]); v[2 * i] = f.x; v[2 * i + 1] = f.y;
                f = __half22float2(kh[i]); k[2 * i] = f.x; k[2 * i + 1] = f.y;
            }
        }
        *(float4*)(Qs + idx)     = make_float4(q[0], q[1], q[2], q[3]);
        *(float4*)(Qs + idx + 4) = make_float4(q[4], q[5], q[6], q[7]);
        *(float4*)(Vs + idx)     = make_float4(v[0], v[1], v[2], v[3]);
        *(float4*)(Vs + idx + 4) = make_float4(v[4], v[5], v[6], v[7]);
        #pragma unroll
        for (int i = 0; i < 8; ++i)
            KTs[(w + i) * 65 + h] = k[i];
        float* qd = Qpk + (h >> 3) * 256 + (h & 7);
        #pragma unroll
        for (int i = 0; i < 8; ++i)
            qd[(w + i) * 8] = q[i];
    }
    __syncthreads();

    // ---- Pool over h pairs; q written packed ----
    #pragma unroll
    for (int i = 0; i < 4; ++i) {
        int idx = t + i * 256;
        int g = idx >> 5, w = idx & 31;
        qpk[(g >> 2) * 128 + w * 4 + (g & 3)] =
            0.5f * (Qs[(2 * g) * 32 + w] + Qs[(2 * g + 1) * 32 + w]);
        kTs[w * 33 + g] = 0.5f * (KTs[w * 65 + 2 * g] + KTs[w * 65 + 2 * g + 1]);
    }
    __syncthreads();

    const int g0 = warp * 4;
    {
        float s0[4] = {0, 0, 0, 0}, s1[4] = {0, 0, 0, 0};
        #pragma unroll
        for (int w = 0; w < 32; ++w) {
            float k0 = KTs[w * 65 + lane];
            float k1 = KTs[w * 65 + 32 + lane];
            float4 qv = *(const float4*)(qpk + warp * 128 + w * 4);
            s0[0] = fmaf(qv.x, k0, s0[0]);  s1[0] = fmaf(qv.x, k1, s1[0]);
            s0[1] = fmaf(qv.y, k0, s0[1]);  s1[1] = fmaf(qv.y, k1, s1[1]);
            s0[2] = fmaf(qv.z, k0, s0[2]);  s1[2] = fmaf(qv.z, k1, s1[2]);
            s0[3] = fmaf(qv.w, k0, s0[3]);  s1[3] = fmaf(qv.w, k1, s1[3]);
        }
        float p0[4], p1[4];
        #pragma unroll
        for (int gi = 0; gi < 4; ++gi) {
            float a = s0[gi] * D_SCALE, b = s1[gi] * D_SCALE;
            float m = fmaxf(a, b);
            #pragma unroll
            for (int o = 16; o; o >>= 1) m = fmaxf(m, __shfl_xor_sync(FULL, m, o));
            float e0 = __expf(a - m), e1 = __expf(b - m);
            float sum = e0 + e1;
            #pragma unroll
            for (int o = 16; o; o >>= 1) sum += __shfl_xor_sync(FULL, sum, o);
            float r = __frcp_rn(sum);
            p0[gi] = e0 * r;
            p1[gi] = e1 * r;
        }
        *(float4*)(Ppk + warp * 256 + lane * 4)        = make_float4(p0[0], p0[1], p0[2], p0[3]);
        *(float4*)(Ppk + warp * 256 + (lane + 32) * 4) = make_float4(p1[0], p1[1], p1[2], p1[3]);
        __syncwarp();

        float acc[4] = {0, 0, 0, 0};
        #pragma unroll 8
        for (int h = 0; h < 64; ++h) {
            float4 p = *(const float4*)(Ppk + warp * 256 + h * 4);
            float v = Vs[h * 32 + lane];
            acc[0] = fmaf(p.x, v, acc[0]);
            acc[1] = fmaf(p.y, v, acc[1]);
            acc[2] = fmaf(p.z, v, acc[2]);
            acc[3] = fmaf(p.w, v, acc[3]);
        }
        Kqvs[(g0 + 0) * 32 + lane] = acc[0];
        Kqvs[(g0 + 1) * 32 + lane] = acc[1];
        Kqvs[(g0 + 2) * 32 + lane] = acc[2];
        Kqvs[(g0 + 3) * 32 + lane] = acc[3];
    }
    __syncthreads();

    const int h0 = warp * 8;
    {
        float s[8] = {0, 0, 0, 0, 0, 0, 0, 0};
        #pragma unroll
        for (int w = 0; w < 32; ++w) {
            float kt = kTs[w * 33 + lane];
            float4 qa = *(const float4*)(Qpk + warp * 256 + w * 8);
            float4 qb = *(const float4*)(Qpk + warp * 256 + w * 8 + 4);
            s[0] = fmaf(qa.x, kt, s[0]);
            s[1] = fmaf(qa.y, kt, s[1]);
            s[2] = fmaf(qa.z, kt, s[2]);
            s[3] = fmaf(qa.w, kt, s[3]);
            s[4] = fmaf(qb.x, kt, s[4]);
            s[5] = fmaf(qb.y, kt, s[5]);
            s[6] = fmaf(qb.z, kt, s[6]);
            s[7] = fmaf(qb.w, kt, s[7]);
        }
        float p2[8];
        #pragma unroll
        for (int hi = 0; hi < 8; ++hi) {
            float a = s[hi] * D_SCALE;
            float m = a;
            #pragma unroll
            for (int o = 16; o; o >>= 1) m = fmaxf(m, __shfl_xor_sync(FULL, m, o));
            float e = __expf(a - m);
            float sum = e;
            #pragma unroll
            for (int o = 16; o; o >>= 1) sum += __shfl_xor_sync(FULL, sum, o);
            p2[hi] = e * __frcp_rn(sum);
        }
        *(float4*)(Ppk + warp * 256 + lane * 8)     = make_float4(p2[0], p2[1], p2[2], p2[3]);
        *(float4*)(Ppk + warp * 256 + lane * 8 + 4) = make_float4(p2[4], p2[5], p2[6], p2[7]);
        __syncwarp();

        float acc[8] = {0, 0, 0, 0, 0, 0, 0, 0};
        #pragma unroll 8
        for (int g = 0; g < 32; ++g) {
            float4 pa = *(const float4*)(Ppk + warp * 256 + g * 8);
            float4 pb = *(const float4*)(Ppk + warp * 256 + g * 8 + 4);
            float kv = Kqvs[g * 32 + lane];
            acc[0] = fmaf(pa.x, kv, acc[0]);
            acc[1] = fmaf(pa.y, kv, acc[1]);
            acc[2] = fmaf(pa.z, kv, acc[2]);
            acc[3] = fmaf(pa.w, kv, acc[3]);
            acc[4] = fmaf(pb.x, kv, acc[4]);
            acc[5] = fmaf(pb.y, kv, acc[5]);
            acc[6] = fmaf(pb.z, kv, acc[6]);
            acc[7] = fmaf(pb.w, kv, acc[7]);
        }
        #pragma unroll
        for (int hi = 0; hi < 8; ++hi)
            Op[(h0 + hi) * 32 + lane] = acc[hi];
    }
}

// ---------------------------------------------------------------------------
// Kernel 3: [B, C, N] -> [B, N, C] transpose (output epilogue, reads g_O).
// ---------------------------------------------------------------------------
__global__ __launch_bounds__(256) void transpose_kernel(float* __restrict__ out)
{
    __shared__ float tile[32][33];
    const int b  = blockIdx.z;
    const int c0 = blockIdx.y * 32;
    const int n0 = blockIdx.x * 32;
    const int tx = threadIdx.x;
    const int ty = threadIdx.y;

    const float* src = g_O + (size_t)b * CDIM * NSEQ;
    #pragma unroll
    for (int i = 0; i < 32; i += 8)
        tile[ty + i][tx] = src[(size_t)(c0 + ty + i) * NSEQ + n0 + tx];
    __syncthreads();
    #pragma unroll
    for (int i = 0; i < 32; i += 8)
        out[((size_t)b * NSEQ + n0 + ty + i) * CDIM + c0 + tx] = tile[tx][ty + i];
}

// ---------------------------------------------------------------------------
extern "C" void kernel_launch(void* const* d_in, const int* in_sizes, int n_in,
                              void* d_out, int out_size)
{
    (void)in_sizes; (void)n_in; (void)out_size;
    const float* X  = (const float*)d_in[0];
    const float* Wq = (const float*)d_in[1];
    const float* bq = (const float*)d_in[2];
    const float* Wk = (const float*)d_in[3];
    const float* bk = (const float*)d_in[4];
    const float* Wv = (const float*)d_in[5];
    const float* bv = (const float*)d_in[6];
    float* out = (float*)d_out;

    // Apk (32KB) + Wpk (32KB) + Th (128*TSTR*2 = 34816B) = 100352 B
    const size_t proj_smem = 4096 * sizeof(uint4) + (size_t)128 * TSTR * sizeof(__half);
    cudaFuncSetAttribute(proj_mma_kernel, cudaFuncAttributeMaxDynamicSharedMemorySize,
                         (int)proj_smem);

    prep_w_kernel<<<dim3(3, 1, 1), 256>>>(Wq, Wk, Wv);
    proj_mma_kernel<<<dim3(1024, 1, 1), 512, proj_smem>>>(X, bq, bk, bv);
    attn_kernel<<<dim3(BATCH * CDIM, 1, 1), 256>>>();
    transpose_kernel<<<dim3(NSEQ / 32, CDIM / 32, BATCH), dim3(32, 8, 1)>>>(out);
}

// round 16
// speedup vs baseline: 1.0714x; 1.0078x over previous
#include <cuda_runtime.h>
#include <cuda_fp16.h>
#include <cstdint>

#define BATCH 64
#define NSEQ  2048
#define CDIM  128
#define HP    64
#define WP    32
#define HG    32   // HP / POOL
#define D_SCALE 0.08838834764831845f  // 1/sqrt(128)

// Scratch: Q,K,V in [B, C, N] (spatial-major) layout, fp16 (sigmoid outputs in
// (0,1)). V plane is overwritten with the fp16 attention output by attn_kernel
// (each CTA exclusively owns its plane; V reads complete at staging; proj
// rewrites it every replay -> deterministic).
__device__ __half g_Qh[(size_t)BATCH * CDIM * NSEQ];
__device__ __half g_Kh[(size_t)BATCH * CDIM * NSEQ];
__device__ __half g_Vh[(size_t)BATCH * CDIM * NSEQ];

// Precomputed W fragments (fp16, 2-ks packed):
// [p][(nt*4+kp)*32+lane] -> uint4 (b0@ks=2kp, b1@ks=2kp, b0@ks=2kp+1, b1@ks=2kp+1)
__device__ uint4 g_Wpk[3 * 2048];

#define TSTR 136   // proj epilogue half-transpose-buffer row stride (halves)

__device__ __forceinline__ uint32_t h2u(__half2 h) {
    return *reinterpret_cast<uint32_t*>(&h);
}

__device__ __forceinline__ void mma_f16(float& d0, float& d1, float& d2, float& d3,
                                        uint32_t a0, uint32_t a1, uint32_t a2, uint32_t a3,
                                        uint32_t b0, uint32_t b1) {
    asm volatile(
        "mma.sync.aligned.m16n8k16.row.col.f32.f16.f16.f32 "
        "{%0,%1,%2,%3}, {%4,%5,%6,%7}, {%8,%9}, {%0,%1,%2,%3};"
        : "+f"(d0), "+f"(d1), "+f"(d2), "+f"(d3)
        : "r"(a0), "r"(a1), "r"(a2), "r"(a3), "r"(b0), "r"(b1));
}

// ---------------------------------------------------------------------------
// Kernel 0: convert W matrices into 2-ks-packed fp16 MMA fragments, once.
// ---------------------------------------------------------------------------
__global__ __launch_bounds__(256) void prep_w_kernel(
    const float* __restrict__ Wq, const float* __restrict__ Wk,
    const float* __restrict__ Wv)
{
    const int p = blockIdx.x;
    const float* W = (p == 0) ? Wq : (p == 1) ? Wk : Wv;
    const int t = threadIdx.x;
    #pragma unroll
    for (int i = 0; i < 8; ++i) {
        const int pos  = t + i * 256;        // 0..2047
        const int lane = pos & 31;
        const int kp   = (pos >> 5) & 3;
        const int nt   = pos >> 7;
        const int gj   = lane >> 2;
        const int s    = lane & 3;
        const int j    = nt * 8 + gj;
        const int ca   = (2 * kp) * 16 + 2 * s;
        const int cb   = ca + 16;
        __half2 x = __floats2half2_rn(W[j * CDIM + ca],     W[j * CDIM + ca + 1]);
        __half2 y = __floats2half2_rn(W[j * CDIM + ca + 8], W[j * CDIM + ca + 9]);
        __half2 z = __floats2half2_rn(W[j * CDIM + cb],     W[j * CDIM + cb + 1]);
        __half2 w = __floats2half2_rn(W[j * CDIM + cb + 8], W[j * CDIM + cb + 9]);
        g_Wpk[p * 2048 + pos] = make_uint4(h2u(x), h2u(y), h2u(z), h2u(w));
    }
}

// ---------------------------------------------------------------------------
// Kernel 1: projection GEMMs (proven R15 version); output stored as fp16.
// ---------------------------------------------------------------------------
__global__ __launch_bounds__(512) void proj_mma_kernel(
    const float* __restrict__ X,
    const float* __restrict__ bq, const float* __restrict__ bk,
    const float* __restrict__ bv)
{
    extern __shared__ uint4 smq[];
    uint4*  Apk = smq;               // [8 mt][8 ks][32 lane]  2048 uint4 (32 KB)
    uint4*  Wpk = smq + 2048;        // [16 nt][4 kp][32 lane] 2048 uint4 (32 KB)
    __half* Th  = (__half*)(smq + 4096);  // [128 j][TSTR] half transpose buf (34 KB)

    const int t    = threadIdx.x;
    const int warp = t >> 5;
    const int lane = t & 31;
    const int M0   = blockIdx.x * 128;
    const int bidx = M0 >> 11;
    const int n0   = M0 & 2047;

    const int g      = lane >> 2;
    const int tid    = lane & 3;
    const int mgroup = warp & 7;
    const int nhalf  = warp >> 3;
    const int mbase  = mgroup * 16;

    // ---- Stage A: pack X into fp16 MMA fragments (once, reused for 3 p's) ----
    #pragma unroll
    for (int i = 0; i < 4; ++i) {
        const int pos = t + i * 512;          // 0..2047
        const int ln  = pos & 31;
        const int ks  = (pos >> 5) & 7;
        const int mt  = pos >> 8;
        const int gg  = ln >> 2;
        const int ss  = ln & 3;
        const int r0  = M0 + mt * 16 + gg;
        const int c0  = ks * 16 + 2 * ss;
        float2 x00 = *(const float2*)(X + (size_t)r0 * CDIM + c0);
        float2 x10 = *(const float2*)(X + (size_t)(r0 + 8) * CDIM + c0);
        float2 x02 = *(const float2*)(X + (size_t)r0 * CDIM + c0 + 8);
        float2 x12 = *(const float2*)(X + (size_t)(r0 + 8) * CDIM + c0 + 8);
        Apk[pos] = make_uint4(h2u(__floats2half2_rn(x00.x, x00.y)),
                              h2u(__floats2half2_rn(x10.x, x10.y)),
                              h2u(__floats2half2_rn(x02.x, x02.y)),
                              h2u(__floats2half2_rn(x12.x, x12.y)));
    }

    #pragma unroll 1
    for (int p = 0; p < 3; ++p) {
        const float* bias = (p == 0) ? bq : (p == 1) ? bk : bv;
        __half* OutT      = (p == 0) ? g_Qh : (p == 1) ? g_Kh : g_Vh;

        // ---- Stage W fragments: straight copy (2048 uint4) ----
        #pragma unroll
        for (int i = 0; i < 4; ++i)
            Wpk[t + i * 512] = g_Wpk[p * 2048 + t + i * 512];
        __syncthreads();

        // ---- MMA mainloop: warp owns 16 m-rows x 64 j-cols (8 nt) ----
        float acc[8][4];
        #pragma unroll
        for (int nt = 0; nt < 8; ++nt)
            #pragma unroll
            for (int q = 0; q < 4; ++q) acc[nt][q] = 0.0f;

        #pragma unroll
        for (int kp = 0; kp < 4; ++kp) {
            uint4 Aa = Apk[(mgroup * 8 + 2 * kp) * 32 + lane];
            uint4 Ab = Apk[(mgroup * 8 + 2 * kp + 1) * 32 + lane];
            #pragma unroll
            for (int nt = 0; nt < 8; ++nt) {
                const int ntg = nhalf * 8 + nt;
                uint4 w = Wpk[(ntg * 4 + kp) * 32 + lane];
                mma_f16(acc[nt][0], acc[nt][1], acc[nt][2], acc[nt][3],
                        Aa.x, Aa.y, Aa.z, Aa.w, w.x, w.y);
                mma_f16(acc[nt][0], acc[nt][1], acc[nt][2], acc[nt][3],
                        Ab.x, Ab.y, Ab.z, Ab.w, w.z, w.w);
            }
        }

        // ---- Epilogue: bias + sigmoid -> half, transpose to [j][m] via Th ----
        #pragma unroll
        for (int nt = 0; nt < 8; ++nt) {
            const int j0 = nhalf * 64 + nt * 8 + 2 * tid;
            const float b0v = __ldg(bias + j0);
            const float b1v = __ldg(bias + j0 + 1);
            float v0 = acc[nt][0] + b0v;
            float v1 = acc[nt][1] + b1v;
            float v2 = acc[nt][2] + b0v;
            float v3 = acc[nt][3] + b1v;
            v0 = 1.0f / (1.0f + __expf(-v0));
            v1 = 1.0f / (1.0f + __expf(-v1));
            v2 = 1.0f / (1.0f + __expf(-v2));
            v3 = 1.0f / (1.0f + __expf(-v3));
            Th[j0 * TSTR + mbase + g]           = __float2half_rn(v0);
            Th[(j0 + 1) * TSTR + mbase + g]     = __float2half_rn(v1);
            Th[j0 * TSTR + mbase + g + 8]       = __float2half_rn(v2);
            Th[(j0 + 1) * TSTR + mbase + g + 8] = __float2half_rn(v3);
        }
        __syncthreads();

        // ---- Coalesced uint4 (8-half) store: OutT[bidx][j][n0 + m] ----
        #pragma unroll
        for (int it = 0; it < 4; ++it) {
            const int idx = t + it * 512;     // 0..2047
            const int j   = idx >> 4;
            const int m8  = (idx & 15) << 3;
            uint4 v = *(const uint4*)(Th + j * TSTR + m8);
            *(uint4*)(OutT + ((size_t)bidx * CDIM + j) * NSEQ + n0 + m8) = v;
        }
        __syncthreads();   // stores read Th; next p overwrites Wpk + Th
    }
}

// ---------------------------------------------------------------------------
// Kernel 2: per-(b,c) dual-softmax attention (proven R15 version); output
// written as fp16 into the retired g_Vh plane.
// ---------------------------------------------------------------------------
__global__ __launch_bounds__(256) void attn_kernel()
{
    const int bc = blockIdx.x;                      // b*128 + c
    const __half* Qp = g_Qh + (size_t)bc * NSEQ;
    const __half* Kp = g_Kh + (size_t)bc * NSEQ;
    const __half* Vp = g_Vh + (size_t)bc * NSEQ;
    __half* Op = g_Vh + (size_t)bc * NSEQ;          // overwrite V plane (fp16)

    __shared__ float Qs[HP * WP];     // [h][w]
    __shared__ float Vs[HP * WP];     // [h][w]
    __shared__ float KTs[WP * 65];    // [w][h], padded
    __shared__ float kTs[WP * 33];    // [w][g], pooled K, padded
    __shared__ float qpk[8 * 128];    // pooled q packed: [g>>2][w*4+(g&3)]
    __shared__ float Qpk[8 * 256];    // Q packed: [h>>3][w*8+(h&7)]
    __shared__ float Kqvs[HG * WP];   // [g][w]
    __shared__ float Ppk[8 * 256];    // probs packed (phase A->B, then C->D)

    const int t    = threadIdx.x;
    const int warp = t >> 5;
    const int lane = t & 31;
    const unsigned FULL = 0xffffffffu;

    // ---- Load 8 halves per array per thread; convert; K transposed; Q packed ----
    {
        const int idx = t * 8;                // 0..2040
        const int h = idx >> 5, w = idx & 31; // w in {0,8,16,24}
        uint4 qr = *(const uint4*)(Qp + idx);
        uint4 vr = *(const uint4*)(Vp + idx);
        uint4 kr = *(const uint4*)(Kp + idx);
        float q[8], v[8], k[8];
        {
            const __half2* qh = (const __half2*)&qr;
            const __half2* vh = (const __half2*)&vr;
            const __half2* kh = (const __half2*)&kr;
            #pragma unroll
            for (int i = 0; i < 4; ++i) {
                float2 f;
                f = __half22float2(qh[i]); q[2 * i] = f.x; q[2 * i + 1] = f.y;
                f = __half22float2(vh[i]); v[2 * i] = f.x; v[2 * i + 1] = f.y;
                f = __half22float2(kh[i]); k[2 * i] = f.x; k[2 * i + 1] = f.y;
            }
        }
        *(float4*)(Qs + idx)     = make_float4(q[0], q[1], q[2], q[3]);
        *(float4*)(Qs + idx + 4) = make_float4(q[4], q[5], q[6], q[7]);
        *(float4*)(Vs + idx)     = make_float4(v[0], v[1], v[2], v[3]);
        *(float4*)(Vs + idx + 4) = make_float4(v[4], v[5], v[6], v[7]);
        #pragma unroll
        for (int i = 0; i < 8; ++i)
            KTs[(w + i) * 65 + h] = k[i];
        float* qd = Qpk + (h >> 3) * 256 + (h & 7);
        #pragma unroll
        for (int i = 0; i < 8; ++i)
            qd[(w + i) * 8] = q[i];
    }
    __syncthreads();

    // ---- Pool over h pairs; q written packed ----
    #pragma unroll
    for (int i = 0; i < 4; ++i) {
        int idx = t + i * 256;
        int g = idx >> 5, w = idx & 31;
        qpk[(g >> 2) * 128 + w * 4 + (g & 3)] =
            0.5f * (Qs[(2 * g) * 32 + w] + Qs[(2 * g + 1) * 32 + w]);
        kTs[w * 33 + g] = 0.5f * (KTs[w * 65 + 2 * g] + KTs[w * 65 + 2 * g + 1]);
    }
    __syncthreads();

    const int g0 = warp * 4;
    {
        float s0[4] = {0, 0, 0, 0}, s1[4] = {0, 0, 0, 0};
        #pragma unroll
        for (int w = 0; w < 32; ++w) {
            float k0 = KTs[w * 65 + lane];
            float k1 = KTs[w * 65 + 32 + lane];
            float4 qv = *(const float4*)(qpk + warp * 128 + w * 4);
            s0[0] = fmaf(qv.x, k0, s0[0]);  s1[0] = fmaf(qv.x, k1, s1[0]);
            s0[1] = fmaf(qv.y, k0, s0[1]);  s1[1] = fmaf(qv.y, k1, s1[1]);
            s0[2] = fmaf(qv.z, k0, s0[2]);  s1[2] = fmaf(qv.z, k1, s1[2]);
            s0[3] = fmaf(qv.w, k0, s0[3]);  s1[3] = fmaf(qv.w, k1, s1[3]);
        }
        float p0[4], p1[4];
        #pragma unroll
        for (int gi = 0; gi < 4; ++gi) {
            float a = s0[gi] * D_SCALE, b = s1[gi] * D_SCALE;
            float m = fmaxf(a, b);
            #pragma unroll
            for (int o = 16; o; o >>= 1) m = fmaxf(m, __shfl_xor_sync(FULL, m, o));
            float e0 = __expf(a - m), e1 = __expf(b - m);
            float sum = e0 + e1;
            #pragma unroll
            for (int o = 16; o; o >>= 1) sum += __shfl_xor_sync(FULL, sum, o);
            float r = __frcp_rn(sum);
            p0[gi] = e0 * r;
            p1[gi] = e1 * r;
        }
        *(float4*)(Ppk + warp * 256 + lane * 4)        = make_float4(p0[0], p0[1], p0[2], p0[3]);
        *(float4*)(Ppk + warp * 256 + (lane + 32) * 4) = make_float4(p1[0], p1[1], p1[2], p1[3]);
        __syncwarp();

        float acc[4] = {0, 0, 0, 0};
        #pragma unroll 8
        for (int h = 0; h < 64; ++h) {
            float4 p = *(const float4*)(Ppk + warp * 256 + h * 4);
            float v = Vs[h * 32 + lane];
            acc[0] = fmaf(p.x, v, acc[0]);
            acc[1] = fmaf(p.y, v, acc[1]);
            acc[2] = fmaf(p.z, v, acc[2]);
            acc[3] = fmaf(p.w, v, acc[3]);
        }
        Kqvs[(g0 + 0) * 32 + lane] = acc[0];
        Kqvs[(g0 + 1) * 32 + lane] = acc[1];
        Kqvs[(g0 + 2) * 32 + lane] = acc[2];
        Kqvs[(g0 + 3) * 32 + lane] = acc[3];
    }
    __syncthreads();

    const int h0 = warp * 8;
    {
        float s[8] = {0, 0, 0, 0, 0, 0, 0, 0};
        #pragma unroll
        for (int w = 0; w < 32; ++w) {
            float kt = kTs[w * 33 + lane];
            float4 qa = *(const float4*)(Qpk + warp * 256 + w * 8);
            float4 qb = *(const float4*)(Qpk + warp * 256 + w * 8 + 4);
            s[0] = fmaf(qa.x, kt, s[0]);
            s[1] = fmaf(qa.y, kt, s[1]);
            s[2] = fmaf(qa.z, kt, s[2]);
            s[3] = fmaf(qa.w, kt, s[3]);
            s[4] = fmaf(qb.x, kt, s[4]);
            s[5] = fmaf(qb.y, kt, s[5]);
            s[6] = fmaf(qb.z, kt, s[6]);
            s[7] = fmaf(qb.w, kt, s[7]);
        }
        float p2[8];
        #pragma unroll
        for (int hi = 0; hi < 8; ++hi) {
            float a = s[hi] * D_SCALE;
            float m = a;
            #pragma unroll
            for (int o = 16; o; o >>= 1) m = fmaxf(m, __shfl_xor_sync(FULL, m, o));
            float e = __expf(a - m);
            float sum = e;
            #pragma unroll
            for (int o = 16; o; o >>= 1) sum += __shfl_xor_sync(FULL, sum, o);
            p2[hi] = e * __frcp_rn(sum);
        }
        *(float4*)(Ppk + warp * 256 + lane * 8)     = make_float4(p2[0], p2[1], p2[2], p2[3]);
        *(float4*)(Ppk + warp * 256 + lane * 8 + 4) = make_float4(p2[4], p2[5], p2[6], p2[7]);
        __syncwarp();

        float acc[8] = {0, 0, 0, 0, 0, 0, 0, 0};
        #pragma unroll 8
        for (int g = 0; g < 32; ++g) {
            float4 pa = *(const float4*)(Ppk + warp * 256 + g * 8);
            float4 pb = *(const float4*)(Ppk + warp * 256 + g * 8 + 4);
            float kv = Kqvs[g * 32 + lane];
            acc[0] = fmaf(pa.x, kv, acc[0]);
            acc[1] = fmaf(pa.y, kv, acc[1]);
            acc[2] = fmaf(pa.z, kv, acc[2]);
            acc[3] = fmaf(pa.w, kv, acc[3]);
            acc[4] = fmaf(pb.x, kv, acc[4]);
            acc[5] = fmaf(pb.y, kv, acc[5]);
            acc[6] = fmaf(pb.z, kv, acc[6]);
            acc[7] = fmaf(pb.w, kv, acc[7]);
        }
        #pragma unroll
        for (int hi = 0; hi < 8; ++hi)
            Op[(h0 + hi) * 32 + lane] = __float2half_rn(acc[hi]);
    }
}

// ---------------------------------------------------------------------------
// Kernel 3: [B, C, N] fp16 -> [B, N, C] fp32 transpose (output epilogue).
// ---------------------------------------------------------------------------
__global__ __launch_bounds__(256) void transpose_kernel(float* __restrict__ out)
{
    __shared__ float tile[32][33];
    const int b  = blockIdx.z;
    const int c0 = blockIdx.y * 32;
    const int n0 = blockIdx.x * 32;
    const int tx = threadIdx.x;
    const int ty = threadIdx.y;

    const __half* src = g_Vh + (size_t)b * CDIM * NSEQ;
    #pragma unroll
    for (int i = 0; i < 32; i += 8)
        tile[ty + i][tx] = __half2float(src[(size_t)(c0 + ty + i) * NSEQ + n0 + tx]);
    __syncthreads();
    #pragma unroll
    for (int i = 0; i < 32; i += 8)
        out[((size_t)b * NSEQ + n0 + ty + i) * CDIM + c0 + tx] = tile[tx][ty + i];
}

// ---------------------------------------------------------------------------
extern "C" void kernel_launch(void* const* d_in, const int* in_sizes, int n_in,
                              void* d_out, int out_size)
{
    (void)in_sizes; (void)n_in; (void)out_size;
    const float* X  = (const float*)d_in[0];
    const float* Wq = (const float*)d_in[1];
    const float* bq = (const float*)d_in[2];
    const float* Wk = (const float*)d_in[3];
    const float* bk = (const float*)d_in[4];
    const float* Wv = (const float*)d_in[5];
    const float* bv = (const float*)d_in[6];
    float* out = (float*)d_out;

    // Apk (32KB) + Wpk (32KB) + Th (128*TSTR*2 = 34816B) = 100352 B
    const size_t proj_smem = 4096 * sizeof(uint4) + (size_t)128 * TSTR * sizeof(__half);
    cudaFuncSetAttribute(proj_mma_kernel, cudaFuncAttributeMaxDynamicSharedMemorySize,
                         (int)proj_smem);

    prep_w_kernel<<<dim3(3, 1, 1), 256>>>(Wq, Wk, Wv);
    proj_mma_kernel<<<dim3(1024, 1, 1), 512, proj_smem>>>(X, bq, bk, bv);
    attn_kernel<<<dim3(BATCH * CDIM, 1, 1), 256>>>();
    transpose_kernel<<<dim3(NSEQ / 32, CDIM / 32, BATCH), dim3(32, 8, 1)>>>(out);
}